// round 5
// baseline (speedup 1.0000x reference)
#include <cuda_runtime.h>
#include <math.h>
#include <stdint.h>

#define N_P 33600
#define N_G 256
#define N_C 80
#define KK  13
#define LEN 16
#define SPLIT 4
#define CHUNK (N_P / SPLIT)          // 8400
#define CH4   (CHUNK / 2)            // 4200 float4 loads per part

typedef unsigned long long u64;
typedef unsigned int u32;

// ---------------- scratch (device globals; no runtime allocation) ----------
__device__ float2 g_pc [(size_t)N_G * N_P];   // column-major {iou, cost}
__device__ float  g_lT [(size_t)N_C * N_P];
__device__ float  g_sT [(size_t)N_C * N_P];
__device__ float  g_mT [(size_t)N_C * N_P];
__device__ float4 g_pk0[N_P];
__device__ float4 g_pk1[N_P];                 // px, py, 1/stride, +-area
__device__ float4 g_gtbox [N_G];
__device__ float4 g_gtmeta[N_G];
__device__ float4 g_vbox  [N_G];
__device__ int    g_glab  [N_G];
__device__ int    g_goff  [N_G];
__device__ int    g_cnt [N_P];
__device__ int    g_mgt [N_P];
__device__ u64    g_skey[N_G * SPLIT * 16];
__device__ float  g_siou[N_G * SPLIT * 16];

// ---------------- fast approx intrinsics ------------------------------------
__device__ __forceinline__ float ex2a(float x){ float r; asm("ex2.approx.f32 %0,%1;" : "=f"(r) : "f"(x)); return r; }
__device__ __forceinline__ float lg2a(float x){ float r; asm("lg2.approx.f32 %0,%1;" : "=f"(r) : "f"(x)); return r; }
__device__ __forceinline__ float sqrta(float x){ float r; asm("sqrt.approx.f32 %0,%1;" : "=f"(r) : "f"(x)); return r; }
__device__ __forceinline__ float rcpa(float x){ float r; asm("rcp.approx.f32 %0,%1;" : "=f"(r) : "f"(x)); return r; }

// ---------------- math helpers ----------------------------------------------
__device__ __forceinline__ float iou_fast(float4 A, float Pw, float4 b, float area_b) {
    float area_a = fabsf(Pw);
    float ltx = fmaxf(A.x, b.x), lty = fmaxf(A.y, b.y);
    float rbx = fminf(A.z, b.z), rby = fminf(A.w, b.w);
    float w = fmaxf(rbx - ltx, 0.0f), h = fmaxf(rby - lty, 0.0f);
    float inter = w * h;
    float uni = (area_a + area_b) - inter;
    return inter * rcpa(fmaxf(uni, 1e-6f));
}

__device__ __forceinline__ float iou_exact(float4 A, float Pw, float4 b, float area_b) {
    float area_a = fabsf(Pw);
    float ltx = fmaxf(A.x, b.x), lty = fmaxf(A.y, b.y);
    float rbx = fminf(A.z, b.z), rby = fminf(A.w, b.w);
    float w = fmaxf(rbx - ltx, 0.0f), h = fmaxf(rby - lty, 0.0f);
    float inter = w * h;
    float uni = (area_a + area_b) - inter;
    return __fdiv_rn(inter, fmaxf(uni, 1e-6f));
}

__device__ __forceinline__ float cost_fast(float iou, float px, float py, float inv_st,
                                           float cx, float cy,
                                           float l, float s, float mm) {
    float dx = px - cx, dy = py - cy;
    float d2 = __fmaf_rn(dx, dx, dy * dy);
    float dist = sqrta(d2) * inv_st;
    float scp = ex2a(__fmaf_rn(dist, 3.321928094887362f, -9.965784284662087f));
    float d = iou - s;
    float scale = d * d;
    float bce = __fmaf_rn(-l, iou, mm);
    float ic = lg2a(iou + 1e-7f) * -2.0794415416798357f;
    return __fmaf_rn(bce, scale, ic + scp);
}

// ---------------- kernel G: GT preprocessing -------------------------------
__global__ void prep_gt_kernel(const float* __restrict__ gtb,
                               const int*   __restrict__ glab) {
    int j = threadIdx.x;
    if (j < N_G) {
        float x1 = gtb[j*4+0], y1 = gtb[j*4+1];
        float x2 = gtb[j*4+2], y2 = gtb[j*4+3];
        g_gtbox[j] = make_float4(x1, y1, x2, y2);
        float area = (x2 - x1) * (y2 - y1);
        bool pad = ((x1 + y1) + (x2 + y2)) > 0.0f;
        g_gtmeta[j] = make_float4(area, (x1 + x2) * 0.5f, (y1 + y2) * 0.5f,
                                  pad ? 1.0f : 0.0f);
        g_vbox[j] = pad ? make_float4(x1, y1, x2, y2)
                        : make_float4(1e30f, 1e30f, -1e30f, -1e30f);
        int lab = glab[j];
        g_glab[j] = lab;
        g_goff[j] = lab * N_P;
    }
}

// ---------------- kernel S: sigmoid/softplus, transposed -------------------
__global__ void __launch_bounds__(256) prep_scores_kernel(const float* __restrict__ ps) {
    __shared__ float sh[80][33];
    int tid = threadIdx.x;
    int i0 = blockIdx.x * 32;
    const float* base = ps + (size_t)i0 * N_C;
    #pragma unroll
    for (int t = tid; t < 32 * 80; t += 256) {
        int i_loc = t / 80;
        int c = t - i_loc * 80;
        sh[c][i_loc] = base[t];
    }
    __syncthreads();
    int i_loc = tid & 31;
    int cbase = tid >> 5;
    #pragma unroll
    for (int cc = cbase; cc < 80; cc += 8) {
        float l = sh[cc][i_loc];
        float e = ex2a(fabsf(l) * -1.4426950408889634f);
        float inv = rcpa(1.0f + e);
        float sig = (l >= 0.0f) ? inv : e * inv;
        float m = __fmaf_rn(lg2a(1.0f + e), 0.6931471805599453f, fmaxf(l, 0.0f));
        int o = cc * N_P + i0 + i_loc;
        g_lT[o] = l;
        g_sT[o] = sig;
        g_mT[o] = m;
    }
}

// ---------------- kernel P: pack priors + valid mask -----------------------
__global__ void __launch_bounds__(256) prep_priors_kernel(const float* __restrict__ priors,
                                                          const float* __restrict__ pb) {
    __shared__ float4 svb[N_G];
    int tid = threadIdx.x;
    svb[tid] = g_vbox[tid];
    __syncthreads();
    int i = blockIdx.x * 256 + tid;
    if (i >= N_P) return;
    float4 PR = ((const float4*)priors)[i];
    float4 A  = ((const float4*)pb)[i];
    float px = PR.x, py = PR.y;
    bool any = false;
    #pragma unroll 8
    for (int j = 0; j < N_G; j++) {
        float4 B = svb[j];
        any |= (px > B.x) && (py > B.y) && (px < B.z) && (py < B.w);
    }
    float area = (A.z - A.x) * (A.w - A.y);
    g_pk0[i] = A;
    g_pk1[i] = make_float4(px, py, rcpa(PR.z), any ? area : -area);
    g_cnt[i] = 0;
}

// ---------------- kernel A: pairwise -> float2 {iou, cost} -----------------
__global__ void __launch_bounds__(256) pair_kernel() {
    __shared__ float4 sb[32], sm[32];
    __shared__ int soff[32];
    int tid = threadIdx.x;
    int j0 = blockIdx.y * 32;
    if (tid < 32) {
        sb[tid]   = g_gtbox[j0 + tid];
        sm[tid]   = g_gtmeta[j0 + tid];
        soff[tid] = g_goff[j0 + tid];
    }
    __syncthreads();
    int i = blockIdx.x * 256 + tid;
    if (i >= N_P) return;

    float4 A = g_pk0[i];
    float4 P = g_pk1[i];
    bool valid = P.w > 0.0f;
    int ofs = j0 * N_P + i;

    #pragma unroll 4
    for (int jj = 0; jj < 32; jj++) {
        float4 b  = sb[jj];
        float4 m4 = sm[jj];
        float iou = iou_fast(A, P.w, b, m4.x);
        float cost = 1e8f;
        if (valid) {
            int o = soff[jj] + i;
            float l = __ldg(&g_lT[o]), s = __ldg(&g_sT[o]), mm = __ldg(&g_mT[o]);
            cost = cost_fast(iou, P.x, P.y, P.z, m4.y, m4.z, l, s, mm);
        }
        g_pc[ofs] = make_float2(iou, cost);
        ofs += N_P;
    }
}

// ---------------- bitonic top-16 merge primitives --------------------------
__device__ __forceinline__ void merge_iou(float* a, const float* o) {
    float c[LEN];
    #pragma unroll
    for (int k = 0; k < LEN; k++) c[k] = fmaxf(a[k], o[LEN-1-k]);
    #pragma unroll
    for (int s = LEN/2; s > 0; s >>= 1) {
        #pragma unroll
        for (int k = 0; k < LEN; k++) {
            if ((k & s) == 0) {
                float lo = c[k], hi = c[k+s];
                c[k]   = fmaxf(lo, hi);
                c[k+s] = fminf(lo, hi);
            }
        }
    }
    #pragma unroll
    for (int k = 0; k < LEN; k++) a[k] = c[k];
}

__device__ __forceinline__ void merge_key(u64* a, const u64* o) {
    u64 c[LEN];
    #pragma unroll
    for (int k = 0; k < LEN; k++) {
        u64 x = a[k], y = o[LEN-1-k];
        c[k] = (x < y) ? x : y;
    }
    #pragma unroll
    for (int s = LEN/2; s > 0; s >>= 1) {
        #pragma unroll
        for (int k = 0; k < LEN; k++) {
            if ((k & s) == 0) {
                u64 lo = c[k], hi = c[k+s];
                u64 mn = (lo < hi) ? lo : hi;
                u64 mx = (lo < hi) ? hi : lo;
                c[k] = mn; c[k+s] = mx;
            }
        }
    }
    #pragma unroll
    for (int k = 0; k < LEN; k++) a[k] = c[k];
}

__device__ __forceinline__ void shfl_merge(u64* ck, float* vi, int off) {
    u64 ok[LEN]; float ovi[LEN];
    #pragma unroll
    for (int k = 0; k < LEN; k++) {
        ok [k] = __shfl_xor_sync(0xFFFFFFFFu, ck[k], off);
        ovi[k] = __shfl_xor_sync(0xFFFFFFFFu, vi[k], off);
    }
    merge_key(ck, ok);
    merge_iou(vi, ovi);
}

// ---------------- insertion helpers ----------------------------------------
__device__ __forceinline__ void ins_iou(float* vi, float v) {
    vi[LEN-1] = v;
    #pragma unroll
    for (int k = LEN-1; k > 0; k--)
        if (vi[k] > vi[k-1]) { float t = vi[k-1]; vi[k-1] = vi[k]; vi[k] = t; }
}
__device__ __forceinline__ void ins_key(u64* ck, u64 key) {
    ck[LEN-1] = key;
    #pragma unroll
    for (int k = LEN-1; k > 0; k--)
        if (ck[k] < ck[k-1]) { u64 t = ck[k-1]; ck[k-1] = ck[k]; ck[k] = t; }
}

// ---------------- kernel T1: per-(GT, part) gated top-13 -------------------
__global__ void __launch_bounds__(256) topk_p1_kernel() {
    int bid = blockIdx.x;
    int j = bid >> 2, part = bid & 3;
    int tid = threadIdx.x;
    int ibase = part * CHUNK;
    const float4* __restrict__ pc4 =
        (const float4*)(g_pc + (size_t)j * N_P + ibase);

    __shared__ u64 s_kthr;          // 13th-best cost key (monotone decreasing)
    __shared__ u32 s_ithr;          // 13th-best iou bits (monotone increasing)
    if (tid == 0) { s_kthr = 0xFFFFFFFFFFFFFFFFull; s_ithr = 0u; }
    __syncthreads();

    volatile u64* vkthr = &s_kthr;
    volatile u32* vithr = &s_ithr;

    float vi[LEN]; u64 ck[LEN];
    #pragma unroll
    for (int k = 0; k < LEN; k++) { vi[k] = 0.0f; ck[k] = 0xFFFFFFFFFFFFFFFFull; }

    for (int t = tid; t < CH4; t += 256) {
        float4 q = __ldg(pc4 + t);              // {iou0,cost0,iou1,cost1}
        u64 kth = *vkthr;
        float ith = __uint_as_float(*vithr);

        if (q.x > ith && q.x > vi[LEN-1]) {
            ins_iou(vi, q.x);
            atomicMax((u32*)&s_ithr, __float_as_uint(vi[KK-1]));
        }
        if (q.z > ith && q.z > vi[LEN-1]) {
            ins_iou(vi, q.z);
            atomicMax((u32*)&s_ithr, __float_as_uint(vi[KK-1]));
        }
        u64 k0 = (((u64)__float_as_uint(q.y)) << 32) | (u32)(ibase + 2*t);
        if (k0 < kth && k0 < ck[LEN-1]) {
            ins_key(ck, k0);
            atomicMin((u64*)&s_kthr, ck[KK-1]);
        }
        u64 k1 = (((u64)__float_as_uint(q.w)) << 32) | (u32)(ibase + 2*t + 1);
        if (k1 < kth && k1 < ck[LEN-1]) {
            ins_key(ck, k1);
            atomicMin((u64*)&s_kthr, ck[KK-1]);
        }
    }

    // warp butterfly merge (5 levels)
    #pragma unroll
    for (int off = 1; off < 32; off <<= 1) shfl_merge(ck, vi, off);

    // cross-warp merge (8 warp lists) in warp 0
    __shared__ u64 s_ck[8][LEN]; __shared__ float s_vi[8][LEN];
    int w = tid >> 5, lane = tid & 31;
    if (lane == 0) {
        #pragma unroll
        for (int k = 0; k < LEN; k++) { s_ck[w][k] = ck[k]; s_vi[w][k] = vi[k]; }
    }
    __syncthreads();
    if (w == 0) {
        if (lane < 8) {
            #pragma unroll
            for (int k = 0; k < LEN; k++) { ck[k] = s_ck[lane][k]; vi[k] = s_vi[lane][k]; }
        } else {
            #pragma unroll
            for (int k = 0; k < LEN; k++) { ck[k] = 0xFFFFFFFFFFFFFFFFull; vi[k] = 0.0f; }
        }
        shfl_merge(ck, vi, 1);
        shfl_merge(ck, vi, 2);
        shfl_merge(ck, vi, 4);
        if (lane == 0) {
            int base = bid * 16;
            #pragma unroll
            for (int k = 0; k < KK; k++) {
                g_skey[base + k] = ck[k];
                g_siou[base + k] = vi[k];
            }
        }
    }
}

// ---------------- kernel T2: 4-way merge, dynamic_ks, scatter --------------
__global__ void topk_p2_kernel() {
    int j = threadIdx.x;   // 256 GTs, 1 block
    const u64*   k0 = g_skey + (j*4 + 0) * 16;
    const u64*   k1 = g_skey + (j*4 + 1) * 16;
    const u64*   k2 = g_skey + (j*4 + 2) * 16;
    const u64*   k3 = g_skey + (j*4 + 3) * 16;
    const float* v0 = g_siou + (j*4 + 0) * 16;
    const float* v1 = g_siou + (j*4 + 1) * 16;
    const float* v2 = g_siou + (j*4 + 2) * 16;
    const float* v3 = g_siou + (j*4 + 3) * 16;

    // iou: 4-way merge of descending lists, sum first 13
    float sum = 0.0f;
    {
        int a = 0, b = 0, c = 0, d = 0;
        #pragma unroll
        for (int r = 0; r < KK; r++) {
            float fa = v0[a], fb = v1[b], fc = v2[c], fd = v3[d];
            float m01 = fmaxf(fa, fb), m23 = fmaxf(fc, fd);
            float m = fmaxf(m01, m23);
            sum += m;
            if (m == fa)      a++;
            else if (m == fb) b++;
            else if (m == fc) c++;
            else              d++;
        }
    }
    int ks = (int)sum;
    if (ks < 1)  ks = 1;
    if (ks > KK) ks = KK;

    // cost: 4-way merge of ascending key lists, scatter first ks
    {
        int a = 0, b = 0, c = 0, d = 0;
        #pragma unroll
        for (int r = 0; r < KK; r++) {
            u64 fa = k0[a], fb = k1[b], fc = k2[c], fd = k3[d];
            u64 m01 = fa < fb ? fa : fb;
            u64 m23 = fc < fd ? fc : fd;
            u64 m = m01 < m23 ? m01 : m23;
            if (m == fa)      a++;
            else if (m == fb) b++;
            else if (m == fc) c++;
            else              d++;
            if (r < ks) {
                int i = (int)(m & 0xFFFFFFFFull);
                atomicAdd(&g_cnt[i], 1);
                g_mgt[i] = j;
            }
        }
    }
}

// ---------------- kernel R: resolve per-prior assignment -------------------
__global__ void __launch_bounds__(256) resolve_kernel(float* __restrict__ out) {
    int i = blockIdx.x * 256 + threadIdx.x;
    if (i >= N_P) return;
    float4 P = g_pk1[i];
    float4 A = g_pk0[i];
    bool valid = P.w > 0.0f;
    int c = g_cnt[i];
    int gsel = 0;
    bool fg = false;
    if (c == 1) {
        gsel = g_mgt[i];
        fg = true;
    } else if (c > 1) {
        fg = true;
        float best = 3.4e38f;
        for (int j = 0; j < N_G; j++) {
            float cj = g_pc[(size_t)j * N_P + i].y;
            if (cj < best) { best = cj; gsel = j; }
        }
    }
    float iou = 0.0f;
    if (fg) {
        iou = iou_exact(A, P.w, g_gtbox[gsel], g_gtmeta[gsel].x);
    }
    bool fin = fg && valid;
    out[i]           = fin ? (float)(gsel + 1)   : 0.0f;
    out[N_P + i]     = fin ? iou                 : -1e8f;
    out[2*N_P + i]   = fin ? (float)g_glab[gsel] : -1.0f;
}

// ---------------- launch ----------------------------------------------------
extern "C" void kernel_launch(void* const* d_in, const int* in_sizes, int n_in,
                              void* d_out, int out_size) {
    const float* pred_scores = (const float*)d_in[0];
    const float* priors      = (const float*)d_in[1];
    const float* pred_bboxes = (const float*)d_in[2];
    const float* gt_bboxes   = (const float*)d_in[3];
    const int*   gt_labels   = (const int*)  d_in[4];

    prep_gt_kernel<<<1, 256>>>(gt_bboxes, gt_labels);
    prep_scores_kernel<<<N_P / 32, 256>>>(pred_scores);
    prep_priors_kernel<<<(N_P + 255) / 256, 256>>>(priors, pred_bboxes);
    dim3 gA((N_P + 255) / 256, 8);
    pair_kernel<<<gA, 256>>>();
    topk_p1_kernel<<<N_G * SPLIT, 256>>>();
    topk_p2_kernel<<<1, 256>>>();
    resolve_kernel<<<(N_P + 255) / 256, 256>>>((float*)d_out);
}